// round 16
// baseline (speedup 1.0000x reference)
#include <cuda_runtime.h>
#include <cuda_bf16.h>
#include <cstdint>

// ---------------------------------------------------------------------------
// GATModel on GB300: tcgen05 bf16 split-GEMM (persistent, 128x128 tiles) +
// two-phase GAT aggregate; classifier FUSED into layer-2 aggregate (fp32).
// R16: remove the 48us single-tile-per-CTA classifier GEMM entirely.
// ---------------------------------------------------------------------------

#if defined(__CUDA_ARCH_FEAT_SM103_ALL) || defined(__CUDA_ARCH_FEAT_SM100_ALL) || \
    defined(__CUDA_ARCH_FEAT_SM101_ALL) || defined(__CUDA_ARCH_SPECIFIC__)
#define TC_OK 1
#else
#define TC_OK 0
#endif

#define NMAX 50000
#define EMAX 500000

__device__ float          g_buf1[NMAX * 256];
__device__ __nv_bfloat16  g_a_hi[NMAX * 256];
__device__ __nv_bfloat16  g_a_lo[NMAX * 256];
__device__ __nv_bfloat16  g_wb_hi[256 * 256];
__device__ __nv_bfloat16  g_wb_lo[256 * 256];
__device__ float g_ssrc[NMAX * 4];
__device__ float g_sdst[NMAX * 4];
__device__ int   g_counts[NMAX];
__device__ int   g_rowbeg[NMAX];
__device__ int   g_rowend[NMAX];
__device__ int   g_cursor[NMAX];
__device__ int   g_csrc[EMAX];
__device__ int   g_is64;
__device__ int   g_total;

// ---------------- edge_index dtype detection ----------------
__global__ void detect_dtype(const void* __restrict__ ei, int N) {
    const long long* p = (const long long*)ei;
    int ok = 1;
    for (int i = 0; i < 16; i++) {
        long long v = p[i];
        if (v < 0 || v >= (long long)N) ok = 0;
    }
    g_is64 = ok;
}
__device__ __forceinline__ int load_idx(const void* ei, long long pos) {
    if (g_is64) return (int)((const long long*)ei)[pos];
    return ((const int*)ei)[pos];
}

// ---------------- CSR build ----------------
__global__ void zero_counts(int N) {
    int i = blockIdx.x * blockDim.x + threadIdx.x;
    if (i < N) g_counts[i] = 0;
    if (i == 0) g_total = 0;
}
__global__ void hist_kernel(const void* __restrict__ ei, int E, int N) {
    int e = blockIdx.x * blockDim.x + threadIdx.x;
    if (e < E) {
        int d = load_idx(ei, (long long)E + e);
        if (d >= 0 && d < N) atomicAdd(&g_counts[d], 1);
    }
}
__global__ void __launch_bounds__(1024)
alloc_rows(int N) {
    __shared__ int sh[1024];
    __shared__ int sbase;
    int tid = threadIdx.x;
    int i = blockIdx.x * 1024 + tid;
    int c = (i < N) ? g_counts[i] : 0;
    sh[tid] = c;
    __syncthreads();
    for (int off = 1; off < 1024; off <<= 1) {
        int v = (tid >= off) ? sh[tid - off] : 0;
        __syncthreads();
        sh[tid] += v;
        __syncthreads();
    }
    if (tid == 1023) sbase = atomicAdd(&g_total, sh[1023]);
    __syncthreads();
    if (i < N) {
        int b = sbase + sh[tid] - c;
        g_rowbeg[i] = b;
        g_rowend[i] = b + c;
        g_cursor[i] = b;
    }
}
__global__ void scatter_kernel(const void* __restrict__ ei, int E, int N) {
    int e = blockIdx.x * blockDim.x + threadIdx.x;
    if (e < E) {
        int d = load_idx(ei, (long long)E + e);
        int s = load_idx(ei, e);
        if (d >= 0 && d < N && s >= 0 && s < N) {
            int pos = atomicAdd(&g_cursor[d], 1);
            if (pos >= 0 && pos < E) g_csrc[pos] = s;
        }
    }
}

// ---------------- fp32 -> bf16 hi/lo split conversions ----------------
__global__ void conv_split_x(const float* __restrict__ src, int n2) {
    int i = blockIdx.x * blockDim.x + threadIdx.x;
    if (i < n2) {
        float2 v = ((const float2*)src)[i];
        __nv_bfloat16 h0 = __float2bfloat16(v.x);
        __nv_bfloat16 h1 = __float2bfloat16(v.y);
        ((__nv_bfloat162*)g_a_hi)[i] = __halves2bfloat162(h0, h1);
        ((__nv_bfloat162*)g_a_lo)[i] = __halves2bfloat162(
            __float2bfloat16(v.x - __bfloat162float(h0)),
            __float2bfloat16(v.y - __bfloat162float(h1)));
    }
}
__global__ void conv_split_w(const float* __restrict__ src, int n2) {
    int i = blockIdx.x * blockDim.x + threadIdx.x;
    if (i < n2) {
        float2 v = ((const float2*)src)[i];
        __nv_bfloat16 h0 = __float2bfloat16(v.x);
        __nv_bfloat16 h1 = __float2bfloat16(v.y);
        ((__nv_bfloat162*)g_wb_hi)[i] = __halves2bfloat162(h0, h1);
        ((__nv_bfloat162*)g_wb_lo)[i] = __halves2bfloat162(
            __float2bfloat16(v.x - __bfloat162float(h0)),
            __float2bfloat16(v.y - __bfloat162float(h1)));
    }
}

// ---------------- tcgen05 helpers (arch-specific pass only) ----------------
#if TC_OK
__device__ __forceinline__ uint32_t elect_one_pred() {
    uint32_t pred;
    asm volatile("{\n\t.reg .pred p;\n\telect.sync _|p, 0xFFFFFFFF;\n\t"
                 "selp.b32 %0, 1, 0, p;\n\t}" : "=r"(pred));
    return pred;
}
__device__ __forceinline__ uint32_t smem_to_u32(const void* p) {
    uint32_t a;
    asm("{ .reg .u64 t; cvta.to.shared.u64 t, %1; cvt.u32.u64 %0, t; }"
        : "=r"(a) : "l"(p));
    return a;
}
#define MBARRIER_INIT(mbar, count) \
    asm volatile("mbarrier.init.shared.b64 [%0], %1;" \
                 :: "r"((uint32_t)(mbar)), "r"((uint32_t)(count)) : "memory")
#define MBARRIER_WAIT_PARITY(mbar, parity) do { \
    uint32_t _m = (uint32_t)(mbar), _p = (uint32_t)(parity), _d; \
    asm volatile("{\n\t.reg .pred p;\n\t" \
        "mbarrier.try_wait.parity.acquire.cta.shared::cta.b64 p, [%1], %2;\n\t" \
        "selp.b32 %0, 1, 0, p;\n\t}" : "=r"(_d) : "r"(_m), "r"(_p) : "memory"); \
    if (!_d) { \
        asm volatile("{\n\t.reg .pred P1;\n\t" \
            "WL_%=:\n\t" \
            "mbarrier.try_wait.parity.acquire.cta.shared::cta.b64 P1, [%0], %1, 0x989680;\n\t" \
            "@P1 bra.uni WD_%=;\n\tbra.uni WL_%=;\n\tWD_%=:\n\t}" \
            :: "r"(_m), "r"(_p) : "memory"); \
    } \
} while (0)
#define TCGEN05_ALLOC(sr, n) \
    asm volatile("tcgen05.alloc.cta_group::1.sync.aligned.shared::cta.b32 [%0], %1;" \
                 :: "r"((uint32_t)(sr)), "r"((uint32_t)(n)) : "memory")
#define TCGEN05_DEALLOC(t, n) \
    asm volatile("tcgen05.dealloc.cta_group::1.sync.aligned.b32 %0, %1;" \
                 :: "r"(t), "r"((uint32_t)(n)))
#define TCGEN05_RELINQ() \
    asm volatile("tcgen05.relinquish_alloc_permit.cta_group::1.sync.aligned;")
#define TCGEN05_COMMIT(mbar) \
    asm volatile("tcgen05.commit.cta_group::1.mbarrier::arrive::one.shared::cluster.b64 [%0];" \
                 :: "r"((uint32_t)(mbar)) : "memory")
#define TCGEN05_FENCE_AFTER() \
    asm volatile("tcgen05.fence::after_thread_sync;" ::: "memory")
#define TCGEN05_FENCE_BEFORE() \
    asm volatile("tcgen05.fence::before_thread_sync;" ::: "memory")
#define TCGEN05_WAIT_LD() \
    asm volatile("tcgen05.wait::ld.sync.aligned;" ::: "memory")
#define TCGEN05_LD_32X32B_X16(r, ta) \
    asm volatile("tcgen05.ld.sync.aligned.32x32b.x16.b32 " \
        "{%0, %1, %2, %3, %4, %5, %6, %7, %8, %9, %10, %11, %12, %13, %14, %15}, [%16];" \
        : "=r"((r)[0]), "=r"((r)[1]), "=r"((r)[2]), "=r"((r)[3]), \
          "=r"((r)[4]), "=r"((r)[5]), "=r"((r)[6]), "=r"((r)[7]), \
          "=r"((r)[8]), "=r"((r)[9]), "=r"((r)[10]), "=r"((r)[11]), \
          "=r"((r)[12]), "=r"((r)[13]), "=r"((r)[14]), "=r"((r)[15]) \
        : "r"(ta))
#define CP_ASYNC16(dst, src) \
    asm volatile("cp.async.cg.shared.global [%0], [%1], 16;" \
                 :: "r"((uint32_t)(dst)), "l"(src) : "memory")
#define CP_COMMIT() \
    asm volatile("cp.async.commit_group;" ::: "memory")
#define CP_WAIT_GROUP(n) \
    asm volatile("cp.async.wait_group %0;" :: "n"(n) : "memory")

__device__ __forceinline__ uint64_t make_desc(uint32_t addr) {
    uint64_t base = (uint64_t(2) << 61) | (uint64_t(1) << 46) |
                    (uint64_t(64) << 32) | (uint64_t(1) << 16);
    return base | ((uint64_t)(addr >> 4) & 0x3FFF);
}
__device__ __forceinline__ void mma_f16_ss(uint32_t d, uint64_t ad, uint64_t bd,
                                           uint32_t idesc, bool en) {
    uint32_t e = en ? 1u : 0u;
    asm volatile("{\n\t.reg .pred p;\n\tsetp.ne.u32 p, %5, 0;\n\t"
                 "tcgen05.mma.cta_group::1.kind::f16 [%0], %1, %2, %3, {%4, %4, %4, %4}, p;\n\t}"
                 :: "r"(d), "l"(ad), "l"(bd), "r"(idesc), "r"(0u), "r"(e)
                 : "memory");
}
#define MMA_IDESC 0x8100490u
#endif  // TC_OK

// ---------------- persistent tcgen05 split-GEMM, 128x128 tiles, occ=3 --------
#define SM_TMEM 0
#define SM_MB0 8
#define SM_BUF 1024
#define OFF_ALO 16384
#define OFF_BHI 32768
#define OFF_BLO 49152
#define SM_TOTAL (1024 + 65536)
#define GEMM_GRID 444

__global__ void __launch_bounds__(256, 3)
gemm_tc(const float* __restrict__ bias,
        float* __restrict__ Cext, int toExt, int M, int Nout,
        const float* __restrict__ a_src, const float* __restrict__ a_dst) {
#if TC_OK
    extern __shared__ char smem[];
    uint32_t sb = smem_to_u32(smem);
    int tid = threadIdx.x;
    int wid = tid >> 5;
    int lane = tid & 31;
    float* C = toExt ? Cext : (float*)g_buf1;

    int nColTiles = (Nout + 127) >> 7;
    int nRows = (M + 127) >> 7;
    int nTiles = nRows * nColTiles;

    if (wid == 0) {
        TCGEN05_ALLOC(sb + SM_TMEM, 128);
        TCGEN05_RELINQ();
    }
    if (tid == 0) MBARRIER_INIT(sb + SM_MB0, 1);
    __syncthreads();
    uint32_t tmem;
    asm volatile("ld.shared.b32 %0, [%1];" : "=r"(tmem) : "r"(sb + SM_TMEM));

    int ar = tid & 127;
    bool a_hi = tid < 128;
    int a_off_base = (ar >> 3) * 1024 + (ar & 7) * 128;
    int a_sub = a_hi ? 0 : OFF_ALO;
    const __nv_bfloat16* a_arr = a_hi ? g_a_hi : g_a_lo;

    int br = tid & 127;
    bool b_is_hi = tid < 128;
    const __nv_bfloat16* b_arr = b_is_hi ? g_wb_hi : g_wb_lo;
    int b_off_base = (br >> 3) * 1024 + (br & 7) * 128;
    int b_sub = b_is_hi ? OFF_BHI : OFF_BLO;

    auto load_stage = [&](int row0, int col0, int s) {
        uint32_t bufb = sb + SM_BUF;
        {
            const uint4* src = (const uint4*)(a_arr + (size_t)(row0 + ar) * 256 + s * 64);
            bool ok = (row0 + ar) < M;
#pragma unroll
            for (int c = 0; c < 8; c++) {
                int off = a_off_base + c * 16;
                off ^= (off >> 3) & 0x70;
                if (ok) CP_ASYNC16(bufb + a_sub + off, src + c);
                else *(uint4*)(smem + SM_BUF + a_sub + off) =
                         make_uint4(0u, 0u, 0u, 0u);
            }
        }
        if (col0 + br < Nout) {
            const uint4* src = (const uint4*)(b_arr + (size_t)(col0 + br) * 256 + s * 64);
#pragma unroll
            for (int c = 0; c < 8; c++) {
                int off = b_off_base + c * 16;
                off ^= (off >> 3) & 0x70;
                CP_ASYNC16(bufb + b_sub + off, src + c);
            }
        }
        CP_COMMIT();
    };

    int mma_phase = 0;
    int t = blockIdx.x;
    if (t < nTiles) {
        load_stage((t / nColTiles) * 128, (t % nColTiles) * 128, 0);
    }

    for (; t < nTiles; t += GEMM_GRID) {
        int row0 = (t / nColTiles) * 128;
        int col0 = (t % nColTiles) * 128;
        int cbMax = min(2, (Nout - col0) >> 6);
        int tn = t + GEMM_GRID;

#pragma unroll
        for (int s = 0; s < 4; s++) {
            CP_WAIT_GROUP(0);
            __syncthreads();
            asm volatile("fence.proxy.async.shared::cta;" ::: "memory");

            if (wid == 0) {
                if (elect_one_pred()) {
                    uint32_t bufb = sb + SM_BUF;
                    uint64_t dA_hi = make_desc(bufb);
                    uint64_t dA_lo = make_desc(bufb + OFF_ALO);
                    uint64_t dB_hi = make_desc(bufb + OFF_BHI);
                    uint64_t dB_lo = make_desc(bufb + OFF_BLO);
#pragma unroll
                    for (int term = 0; term < 3; term++) {
                        uint64_t da = (term == 2) ? dA_lo : dA_hi;
                        uint64_t db = (term == 1) ? dB_lo : dB_hi;
#pragma unroll
                        for (int kc = 0; kc < 4; kc++) {
                            bool en = !(s == 0 && term == 0 && kc == 0);
                            for (int cb = 0; cb < cbMax; cb++) {
                                mma_f16_ss(tmem + cb * 64, da + kc * 2,
                                           db + cb * 512 + kc * 2, MMA_IDESC, en);
                            }
                        }
                    }
                    TCGEN05_COMMIT(sb + SM_MB0);
                }
            }
            MBARRIER_WAIT_PARITY(sb + SM_MB0, mma_phase & 1);
            mma_phase++;

            if (s < 3) {
                load_stage(row0, col0, s + 1);
            } else if (tn < nTiles) {
                load_stage((tn / nColTiles) * 128, (tn % nColTiles) * 128, 0);
            }
        }

        TCGEN05_FENCE_AFTER();

        if (wid < 4) {
            int r = row0 + wid * 32 + lane;
            for (int cb = 0; cb < cbMax; cb++) {
                int head = (col0 >> 6) + cb;
                float vs = 0.f, vd = 0.f;
#pragma unroll
                for (int ch = 0; ch < 4; ch++) {
                    uint32_t d[16];
                    TCGEN05_LD_32X32B_X16(d, tmem + cb * 64 + ch * 16);
                    TCGEN05_WAIT_LD();
                    if (r < M) {
                        int cbase = col0 + cb * 64 + ch * 16;
                        float cv[16];
#pragma unroll
                        for (int j = 0; j < 16; j++) {
                            cv[j] = __uint_as_float(d[j]);
                            if (bias) cv[j] += bias[cbase + j];
                        }
                        float* crow = C + (size_t)r * Nout + cbase;
#pragma unroll
                        for (int q = 0; q < 4; q++) {
                            *(float4*)(crow + q * 4) = make_float4(
                                cv[4 * q], cv[4 * q + 1], cv[4 * q + 2], cv[4 * q + 3]);
                        }
                        if (a_src) {
#pragma unroll
                            for (int j = 0; j < 16; j++) {
                                vs = fmaf(cv[j], a_src[cbase + j], vs);
                                vd = fmaf(cv[j], a_dst[cbase + j], vd);
                            }
                        }
                    }
                }
                if (a_src && r < M) {
                    g_ssrc[r * 4 + head] = vs;
                    g_sdst[r * 4 + head] = vd;
                }
            }
            TCGEN05_FENCE_BEFORE();
        }
        __syncthreads();
    }

    __syncthreads();
    if (tid == 0)
        asm volatile("mbarrier.inval.shared.b64 [%0];" :: "r"(sb + SM_MB0) : "memory");
    if (wid == 0) TCGEN05_DEALLOC(tmem, 128);
#endif  // TC_OK
}

// ---------------- GAT aggregate + BN + ELU; optional fused classifier --------
// mode 0: emit bf16 hi/lo for next GEMM. mode 1: out[n,:]=h@Wc^T+bc (fp32).
__global__ void __launch_bounds__(128)
gat_agg(const float* __restrict__ gamma, const float* __restrict__ beta,
        const float* __restrict__ mean, const float* __restrict__ var,
        const float* __restrict__ Wc, const float* __restrict__ bc,
        float* __restrict__ out, int mode) {
    __shared__ float wgt[32][4];
    __shared__ int   sidx[32];
    __shared__ float smax[4];
    __shared__ float sh_h[256];
    __shared__ float sh_part[128];

    int n = blockIdx.x;
    int tid = threadIdx.x;
    int head = tid >> 5;
    int lane = tid & 31;
    int beg = g_rowbeg[n];
    int end = g_rowend[n];
    const float* hfeat = g_buf1;

    {
        float sd_h = g_sdst[n * 4 + head];
        float m = 0.f;
        for (int i = beg + lane; i < end; i += 32) {
            int s = g_csrc[i];
            float e = g_ssrc[s * 4 + head] + sd_h;
            e = (e >= 0.f) ? e : 0.2f * e;
            m = fmaxf(m, e);
        }
#pragma unroll
        for (int o = 16; o; o >>= 1) m = fmaxf(m, __shfl_xor_sync(~0u, m, o));
        if (lane == 0) smax[head] = m;
    }
    __syncthreads();

    int eh = tid & 3;
    int eo = tid >> 2;
    float sd_eh = g_sdst[n * 4 + eh];
    float m_eh = smax[eh];

    float acc0 = 0.f, acc1 = 0.f, ws = 0.f;
    int c = tid * 2;

    for (int base = beg; base < end; base += 32) {
        int cnt = min(32, end - base);
        {
            float w = 0.f;
            int s = -1;
            if (eo < cnt) {
                s = g_csrc[base + eo];
                float e = g_ssrc[s * 4 + eh] + sd_eh;
                e = (e >= 0.f) ? e : 0.2f * e;
                w = __expf(e - m_eh);
            }
            wgt[eo][eh] = w;
            if (eh == 0) sidx[eo] = s;
        }
        __syncthreads();
        int j = 0;
        for (; j + 4 <= cnt; j += 4) {
            float w0 = wgt[j][head], w1 = wgt[j + 1][head];
            float w2 = wgt[j + 2][head], w3 = wgt[j + 3][head];
            float2 h0 = *(const float2*)&hfeat[(size_t)sidx[j] * 256 + c];
            float2 h1 = *(const float2*)&hfeat[(size_t)sidx[j + 1] * 256 + c];
            float2 h2 = *(const float2*)&hfeat[(size_t)sidx[j + 2] * 256 + c];
            float2 h3 = *(const float2*)&hfeat[(size_t)sidx[j + 3] * 256 + c];
            ws += (w0 + w1) + (w2 + w3);
            acc0 = fmaf(w0, h0.x, acc0); acc1 = fmaf(w0, h0.y, acc1);
            acc0 = fmaf(w1, h1.x, acc0); acc1 = fmaf(w1, h1.y, acc1);
            acc0 = fmaf(w2, h2.x, acc0); acc1 = fmaf(w2, h2.y, acc1);
            acc0 = fmaf(w3, h3.x, acc0); acc1 = fmaf(w3, h3.y, acc1);
        }
        for (; j < cnt; j++) {
            float w = wgt[j][head];
            ws += w;
            float2 hv = *(const float2*)&hfeat[(size_t)sidx[j] * 256 + c];
            acc0 = fmaf(w, hv.x, acc0);
            acc1 = fmaf(w, hv.y, acc1);
        }
        __syncthreads();
    }

    float inv = 1.f / fmaxf(ws, 1e-9f);
    float o0 = acc0 * inv;
    float o1 = acc1 * inv;

    o0 = (o0 - mean[c]) * rsqrtf(var[c] + 1e-5f) * gamma[c] + beta[c];
    o1 = (o1 - mean[c + 1]) * rsqrtf(var[c + 1] + 1e-5f) * gamma[c + 1] + beta[c + 1];
    o0 = (o0 > 0.f) ? o0 : expm1f(o0);
    o1 = (o1 > 0.f) ? o1 : expm1f(o1);

    if (mode == 0) {
        __nv_bfloat16 h0 = __float2bfloat16(o0);
        __nv_bfloat16 h1 = __float2bfloat16(o1);
        size_t idx2 = ((size_t)n * 256 + c) >> 1;
        ((__nv_bfloat162*)g_a_hi)[idx2] = __halves2bfloat162(h0, h1);
        ((__nv_bfloat162*)g_a_lo)[idx2] = __halves2bfloat162(
            __float2bfloat16(o0 - __bfloat162float(h0)),
            __float2bfloat16(o1 - __bfloat162float(h1)));
    } else {
        // fused classifier: out[n,j] = sum_c h[c]*Wc[j,c] + bc[j]  (fp32 exact)
        sh_h[c] = o0;
        sh_h[c + 1] = o1;
        __syncthreads();
        int j = tid & 63;
        int half = tid >> 6;           // 0 or 1: channels [0,128) or [128,256)
        const float4* wrow = (const float4*)(Wc + (size_t)j * 256 + half * 128);
        const float4* hh = (const float4*)(sh_h + half * 128);
        float s = 0.f;
#pragma unroll
        for (int q = 0; q < 32; q++) {
            float4 hv = hh[q];
            float4 wv = wrow[q];
            s = fmaf(hv.x, wv.x, s);
            s = fmaf(hv.y, wv.y, s);
            s = fmaf(hv.z, wv.z, s);
            s = fmaf(hv.w, wv.w, s);
        }
        sh_part[tid] = s;
        __syncthreads();
        if (tid < 64)
            out[(size_t)n * 64 + tid] = sh_part[tid] + sh_part[tid + 64] + bc[tid];
    }
}

// ---------------------------------------------------------------------------
extern "C" void kernel_launch(void* const* d_in, const int* in_sizes, int n_in,
                              void* d_out, int out_size) {
    const float* x   = (const float*)d_in[0];
    const void*  ei  = d_in[1];
    const float* W1  = (const float*)d_in[2];
    const float* as1 = (const float*)d_in[3];
    const float* ad1 = (const float*)d_in[4];
    const float* g1  = (const float*)d_in[5];
    const float* b1  = (const float*)d_in[6];
    const float* m1  = (const float*)d_in[7];
    const float* v1  = (const float*)d_in[8];
    const float* W2  = (const float*)d_in[9];
    const float* as2 = (const float*)d_in[10];
    const float* ad2 = (const float*)d_in[11];
    const float* g2  = (const float*)d_in[12];
    const float* b2  = (const float*)d_in[13];
    const float* m2  = (const float*)d_in[14];
    const float* v2  = (const float*)d_in[15];
    const float* Wc  = (const float*)d_in[16];
    const float* bc  = (const float*)d_in[17];
    float* out = (float*)d_out;

    int N = in_sizes[0] / 256;
    int E = in_sizes[1] / 2;

    cudaFuncSetAttribute(gemm_tc, cudaFuncAttributeMaxDynamicSharedMemorySize,
                         SM_TOTAL);

    int nx2 = N * 128;
    int nw2 = 256 * 256 / 2;

    // gemm_tc stays the 4th launch for ncu.
    conv_split_x<<<(nx2 + 255) / 256, 256>>>(x, nx2);              // 1
    conv_split_w<<<(nw2 + 255) / 256, 256>>>(W1, nw2);             // 2
    detect_dtype<<<1, 1>>>(ei, N);                                 // 3
    gemm_tc<<<GEMM_GRID, 256, SM_TOTAL>>>(nullptr, nullptr, 0, N, 256, as1, ad1); // 4
    zero_counts<<<(N + 255) / 256, 256>>>(N);                      // 5
    hist_kernel<<<(E + 255) / 256, 256>>>(ei, E, N);               // 6
    alloc_rows<<<(N + 1023) / 1024, 1024>>>(N);                    // 7
    scatter_kernel<<<(E + 255) / 256, 256>>>(ei, E, N);            // 8
    gat_agg<<<N, 128>>>(g1, b1, m1, v1, nullptr, nullptr, nullptr, 0); // 9

    // --- layer 2 ---
    conv_split_w<<<(nw2 + 255) / 256, 256>>>(W2, nw2);
    gemm_tc<<<GEMM_GRID, 256, SM_TOTAL>>>(nullptr, nullptr, 0, N, 256, as2, ad2);
    // layer-2 aggregate with FUSED fp32 classifier (replaces classifier GEMM)
    gat_agg<<<N, 128>>>(g2, b2, m2, v2, Wc, bc, out, 1);
}

// round 17
// speedup vs baseline: 3.2704x; 3.2704x over previous
#include <cuda_runtime.h>
#include <cuda.h>
#include <cuda_bf16.h>
#include <cstdint>

// ---------------------------------------------------------------------------
// GATModel on GB300: tcgen05 bf16 split-GEMM with TMA staging (UTMALDG),
// persistent 128x128 tiles, occ=3; two-phase GAT aggregate; separate
// classifier GEMM (R16's fused classifier reverted: 3.2GB Wc re-read).
// R17: replace 4096 cp.async/stage (LSU-issue-bound) with 4 TMA loads/stage.
// ---------------------------------------------------------------------------

#if defined(__CUDA_ARCH_FEAT_SM103_ALL) || defined(__CUDA_ARCH_FEAT_SM100_ALL) || \
    defined(__CUDA_ARCH_FEAT_SM101_ALL) || defined(__CUDA_ARCH_SPECIFIC__)
#define TC_OK 1
#else
#define TC_OK 0
#endif

#define NMAX 50000
#define EMAX 500000

__device__ float          g_buf1[NMAX * 256];
__device__ __nv_bfloat16  g_a_hi[NMAX * 256];
__device__ __nv_bfloat16  g_a_lo[NMAX * 256];
__device__ __nv_bfloat16  g_wb_hi[256 * 256];
__device__ __nv_bfloat16  g_wb_lo[256 * 256];
__device__ float g_ssrc[NMAX * 4];
__device__ float g_sdst[NMAX * 4];
__device__ int   g_counts[NMAX];
__device__ int   g_rowbeg[NMAX];
__device__ int   g_rowend[NMAX];
__device__ int   g_cursor[NMAX];
__device__ int   g_csrc[EMAX];
__device__ int   g_is64;
__device__ int   g_total;

// ---------------- edge_index dtype detection ----------------
__global__ void detect_dtype(const void* __restrict__ ei, int N) {
    const long long* p = (const long long*)ei;
    int ok = 1;
    for (int i = 0; i < 16; i++) {
        long long v = p[i];
        if (v < 0 || v >= (long long)N) ok = 0;
    }
    g_is64 = ok;
}
__device__ __forceinline__ int load_idx(const void* ei, long long pos) {
    if (g_is64) return (int)((const long long*)ei)[pos];
    return ((const int*)ei)[pos];
}

// ---------------- CSR build ----------------
__global__ void zero_counts(int N) {
    int i = blockIdx.x * blockDim.x + threadIdx.x;
    if (i < N) g_counts[i] = 0;
    if (i == 0) g_total = 0;
}
__global__ void hist_kernel(const void* __restrict__ ei, int E, int N) {
    int e = blockIdx.x * blockDim.x + threadIdx.x;
    if (e < E) {
        int d = load_idx(ei, (long long)E + e);
        if (d >= 0 && d < N) atomicAdd(&g_counts[d], 1);
    }
}
__global__ void __launch_bounds__(1024)
alloc_rows(int N) {
    __shared__ int sh[1024];
    __shared__ int sbase;
    int tid = threadIdx.x;
    int i = blockIdx.x * 1024 + tid;
    int c = (i < N) ? g_counts[i] : 0;
    sh[tid] = c;
    __syncthreads();
    for (int off = 1; off < 1024; off <<= 1) {
        int v = (tid >= off) ? sh[tid - off] : 0;
        __syncthreads();
        sh[tid] += v;
        __syncthreads();
    }
    if (tid == 1023) sbase = atomicAdd(&g_total, sh[1023]);
    __syncthreads();
    if (i < N) {
        int b = sbase + sh[tid] - c;
        g_rowbeg[i] = b;
        g_rowend[i] = b + c;
        g_cursor[i] = b;
    }
}
__global__ void scatter_kernel(const void* __restrict__ ei, int E, int N) {
    int e = blockIdx.x * blockDim.x + threadIdx.x;
    if (e < E) {
        int d = load_idx(ei, (long long)E + e);
        int s = load_idx(ei, e);
        if (d >= 0 && d < N && s >= 0 && s < N) {
            int pos = atomicAdd(&g_cursor[d], 1);
            if (pos >= 0 && pos < E) g_csrc[pos] = s;
        }
    }
}

// ---------------- fp32 -> bf16 hi/lo split conversions ----------------
__global__ void conv_split_x(const float* __restrict__ src, int n2) {
    int i = blockIdx.x * blockDim.x + threadIdx.x;
    if (i < n2) {
        float2 v = ((const float2*)src)[i];
        __nv_bfloat16 h0 = __float2bfloat16(v.x);
        __nv_bfloat16 h1 = __float2bfloat16(v.y);
        ((__nv_bfloat162*)g_a_hi)[i] = __halves2bfloat162(h0, h1);
        ((__nv_bfloat162*)g_a_lo)[i] = __halves2bfloat162(
            __float2bfloat16(v.x - __bfloat162float(h0)),
            __float2bfloat16(v.y - __bfloat162float(h1)));
    }
}
__global__ void conv_split_w(const float* __restrict__ src, int n2) {
    int i = blockIdx.x * blockDim.x + threadIdx.x;
    if (i < n2) {
        float2 v = ((const float2*)src)[i];
        __nv_bfloat16 h0 = __float2bfloat16(v.x);
        __nv_bfloat16 h1 = __float2bfloat16(v.y);
        ((__nv_bfloat162*)g_wb_hi)[i] = __halves2bfloat162(h0, h1);
        ((__nv_bfloat162*)g_wb_lo)[i] = __halves2bfloat162(
            __float2bfloat16(v.x - __bfloat162float(h0)),
            __float2bfloat16(v.y - __bfloat162float(h1)));
    }
}

// ---------------- tcgen05 / TMA helpers (arch-specific pass only) ------------
#if TC_OK
__device__ __forceinline__ uint32_t elect_one_pred() {
    uint32_t pred;
    asm volatile("{\n\t.reg .pred p;\n\telect.sync _|p, 0xFFFFFFFF;\n\t"
                 "selp.b32 %0, 1, 0, p;\n\t}" : "=r"(pred));
    return pred;
}
__device__ __forceinline__ uint32_t smem_to_u32(const void* p) {
    uint32_t a;
    asm("{ .reg .u64 t; cvta.to.shared.u64 t, %1; cvt.u32.u64 %0, t; }"
        : "=r"(a) : "l"(p));
    return a;
}
#define MBARRIER_INIT(mbar, count) \
    asm volatile("mbarrier.init.shared.b64 [%0], %1;" \
                 :: "r"((uint32_t)(mbar)), "r"((uint32_t)(count)) : "memory")
#define MBARRIER_EXPECT_TX(mbar, bytes) \
    asm volatile("mbarrier.arrive.expect_tx.shared.b64 _, [%0], %1;" \
                 :: "r"((uint32_t)(mbar)), "r"((uint32_t)(bytes)) : "memory")
#define MBARRIER_WAIT_PARITY(mbar, parity) do { \
    uint32_t _m = (uint32_t)(mbar), _p = (uint32_t)(parity), _d; \
    asm volatile("{\n\t.reg .pred p;\n\t" \
        "mbarrier.try_wait.parity.acquire.cta.shared::cta.b64 p, [%1], %2;\n\t" \
        "selp.b32 %0, 1, 0, p;\n\t}" : "=r"(_d) : "r"(_m), "r"(_p) : "memory"); \
    if (!_d) { \
        asm volatile("{\n\t.reg .pred P1;\n\t" \
            "WL_%=:\n\t" \
            "mbarrier.try_wait.parity.acquire.cta.shared::cta.b64 P1, [%0], %1, 0x989680;\n\t" \
            "@P1 bra.uni WD_%=;\n\tbra.uni WL_%=;\n\tWD_%=:\n\t}" \
            :: "r"(_m), "r"(_p) : "memory"); \
    } \
} while (0)
#define TMA_LOAD_2D(smem_addr, map_ptr, cx, cy, mbar) \
    asm volatile("cp.async.bulk.tensor.2d.shared::cta.global.tile.mbarrier::complete_tx::bytes " \
                 "[%0], [%1, {%2, %3}], [%4];" \
                 :: "r"((uint32_t)(smem_addr)), "l"(map_ptr), \
                    "r"((int)(cx)), "r"((int)(cy)), "r"((uint32_t)(mbar)) : "memory")
#define TCGEN05_ALLOC(sr, n) \
    asm volatile("tcgen05.alloc.cta_group::1.sync.aligned.shared::cta.b32 [%0], %1;" \
                 :: "r"((uint32_t)(sr)), "r"((uint32_t)(n)) : "memory")
#define TCGEN05_DEALLOC(t, n) \
    asm volatile("tcgen05.dealloc.cta_group::1.sync.aligned.b32 %0, %1;" \
                 :: "r"(t), "r"((uint32_t)(n)))
#define TCGEN05_RELINQ() \
    asm volatile("tcgen05.relinquish_alloc_permit.cta_group::1.sync.aligned;")
#define TCGEN05_COMMIT(mbar) \
    asm volatile("tcgen05.commit.cta_group::1.mbarrier::arrive::one.shared::cluster.b64 [%0];" \
                 :: "r"((uint32_t)(mbar)) : "memory")
#define TCGEN05_FENCE_AFTER() \
    asm volatile("tcgen05.fence::after_thread_sync;" ::: "memory")
#define TCGEN05_FENCE_BEFORE() \
    asm volatile("tcgen05.fence::before_thread_sync;" ::: "memory")
#define TCGEN05_WAIT_LD() \
    asm volatile("tcgen05.wait::ld.sync.aligned;" ::: "memory")
#define TCGEN05_LD_32X32B_X16(r, ta) \
    asm volatile("tcgen05.ld.sync.aligned.32x32b.x16.b32 " \
        "{%0, %1, %2, %3, %4, %5, %6, %7, %8, %9, %10, %11, %12, %13, %14, %15}, [%16];" \
        : "=r"((r)[0]), "=r"((r)[1]), "=r"((r)[2]), "=r"((r)[3]), \
          "=r"((r)[4]), "=r"((r)[5]), "=r"((r)[6]), "=r"((r)[7]), \
          "=r"((r)[8]), "=r"((r)[9]), "=r"((r)[10]), "=r"((r)[11]), \
          "=r"((r)[12]), "=r"((r)[13]), "=r"((r)[14]), "=r"((r)[15]) \
        : "r"(ta))

__device__ __forceinline__ uint64_t make_desc(uint32_t addr) {
    uint64_t base = (uint64_t(2) << 61) | (uint64_t(1) << 46) |
                    (uint64_t(64) << 32) | (uint64_t(1) << 16);
    return base | ((uint64_t)(addr >> 4) & 0x3FFF);
}
__device__ __forceinline__ void mma_f16_ss(uint32_t d, uint64_t ad, uint64_t bd,
                                           uint32_t idesc, bool en) {
    uint32_t e = en ? 1u : 0u;
    asm volatile("{\n\t.reg .pred p;\n\tsetp.ne.u32 p, %5, 0;\n\t"
                 "tcgen05.mma.cta_group::1.kind::f16 [%0], %1, %2, %3, {%4, %4, %4, %4}, p;\n\t}"
                 :: "r"(d), "l"(ad), "l"(bd), "r"(idesc), "r"(0u), "r"(e)
                 : "memory");
}
#define MMA_IDESC 0x8100490u
#endif  // TC_OK

// ---------------- persistent tcgen05 split-GEMM, TMA staging, occ=3 ----------
// Tile C[128,128] (two N64 col-blocks). 4 K-stages of 64 through one 64KB
// buffer: A_hi 16K | A_lo 16K | B_hi 16K | B_lo 16K, each filled by ONE
// TMA load (box 64 elems x 128 rows, SW128 => 8-row/1KB atom layout).
#define SM_TMEM 0
#define SM_MBL 8
#define SM_MBM 16
#define SM_BUF 1024
#define OFF_ALO 16384
#define OFF_BHI 32768
#define OFF_BLO 49152
#define SM_TOTAL (1024 + 65536)
#define GEMM_GRID 444
#define STG_BYTES 65536

__global__ void __launch_bounds__(256, 3)
gemm_tc(const float* __restrict__ bias,
        float* __restrict__ Cext, int toExt, int M, int Nout,
        const float* __restrict__ a_src, const float* __restrict__ a_dst,
        const __grid_constant__ CUtensorMap mAhi,
        const __grid_constant__ CUtensorMap mAlo,
        const __grid_constant__ CUtensorMap mBhi,
        const __grid_constant__ CUtensorMap mBlo) {
#if TC_OK
    extern __shared__ char smem[];
    uint32_t sb = smem_to_u32(smem);
    int tid = threadIdx.x;
    int wid = tid >> 5;
    int lane = tid & 31;
    float* C = toExt ? Cext : (float*)g_buf1;

    int nColTiles = (Nout + 127) >> 7;
    int nRows = (M + 127) >> 7;
    int nTiles = nRows * nColTiles;

    if (wid == 0) {
        TCGEN05_ALLOC(sb + SM_TMEM, 128);
        TCGEN05_RELINQ();
    }
    if (tid == 0) {
        MBARRIER_INIT(sb + SM_MBL, 1);
        MBARRIER_INIT(sb + SM_MBM, 1);
    }
    __syncthreads();
    uint32_t tmem;
    asm volatile("ld.shared.b32 %0, [%1];" : "=r"(tmem) : "r"(sb + SM_TMEM));

    int ld_ph = 0, mma_ph = 0;

    for (int t = blockIdx.x; t < nTiles; t += GEMM_GRID) {
        int row0 = (t / nColTiles) * 128;
        int col0 = (t % nColTiles) * 128;
        int cbMax = min(2, (Nout - col0) >> 6);

#pragma unroll
        for (int s = 0; s < 4; s++) {
            // buffer-reuse guard: previous stage's MMA must be done (s>0;
            // tile boundary is covered by the final wait + __syncthreads)
            if (s > 0) {
                MBARRIER_WAIT_PARITY(sb + SM_MBM, mma_ph & 1);
                mma_ph++;
            }
            if (wid == 0) {
                if (elect_one_pred()) {
                    MBARRIER_EXPECT_TX(sb + SM_MBL, STG_BYTES);
                    TMA_LOAD_2D(sb + SM_BUF,           &mAhi, s * 64, row0, sb + SM_MBL);
                    TMA_LOAD_2D(sb + SM_BUF + OFF_ALO, &mAlo, s * 64, row0, sb + SM_MBL);
                    TMA_LOAD_2D(sb + SM_BUF + OFF_BHI, &mBhi, s * 64, col0, sb + SM_MBL);
                    TMA_LOAD_2D(sb + SM_BUF + OFF_BLO, &mBlo, s * 64, col0, sb + SM_MBL);
                }
            }
            MBARRIER_WAIT_PARITY(sb + SM_MBL, ld_ph & 1);
            ld_ph++;

            if (wid == 0) {
                if (elect_one_pred()) {
                    uint64_t dA_hi = make_desc(sb + SM_BUF);
                    uint64_t dA_lo = make_desc(sb + SM_BUF + OFF_ALO);
                    uint64_t dB_hi = make_desc(sb + SM_BUF + OFF_BHI);
                    uint64_t dB_lo = make_desc(sb + SM_BUF + OFF_BLO);
#pragma unroll
                    for (int term = 0; term < 3; term++) {
                        uint64_t da = (term == 2) ? dA_lo : dA_hi;
                        uint64_t db = (term == 1) ? dB_lo : dB_hi;
#pragma unroll
                        for (int kc = 0; kc < 4; kc++) {
                            bool en = !(s == 0 && term == 0 && kc == 0);
                            for (int cb = 0; cb < cbMax; cb++) {
                                mma_f16_ss(tmem + cb * 64, da + kc * 2,
                                           db + cb * 512 + kc * 2, MMA_IDESC, en);
                            }
                        }
                    }
                    TCGEN05_COMMIT(sb + SM_MBM);
                }
            }
        }

        // final MMA of this tile
        MBARRIER_WAIT_PARITY(sb + SM_MBM, mma_ph & 1);
        mma_ph++;
        TCGEN05_FENCE_AFTER();

        // ---- epilogue: x16 chunks, per col-block ----
        if (wid < 4) {
            int r = row0 + wid * 32 + lane;
            for (int cb = 0; cb < cbMax; cb++) {
                int head = (col0 >> 6) + cb;
                float vs = 0.f, vd = 0.f;
#pragma unroll
                for (int ch = 0; ch < 4; ch++) {
                    uint32_t d[16];
                    TCGEN05_LD_32X32B_X16(d, tmem + cb * 64 + ch * 16);
                    TCGEN05_WAIT_LD();
                    if (r < M) {
                        int cbase = col0 + cb * 64 + ch * 16;
                        float cv[16];
#pragma unroll
                        for (int j = 0; j < 16; j++) {
                            cv[j] = __uint_as_float(d[j]);
                            if (bias) cv[j] += bias[cbase + j];
                        }
                        float* crow = C + (size_t)r * Nout + cbase;
#pragma unroll
                        for (int q = 0; q < 4; q++) {
                            *(float4*)(crow + q * 4) = make_float4(
                                cv[4 * q], cv[4 * q + 1], cv[4 * q + 2], cv[4 * q + 3]);
                        }
                        if (a_src) {
#pragma unroll
                            for (int j = 0; j < 16; j++) {
                                vs = fmaf(cv[j], a_src[cbase + j], vs);
                                vd = fmaf(cv[j], a_dst[cbase + j], vd);
                            }
                        }
                    }
                }
                if (a_src && r < M) {
                    g_ssrc[r * 4 + head] = vs;
                    g_sdst[r * 4 + head] = vd;
                }
            }
            TCGEN05_FENCE_BEFORE();
        }
        __syncthreads();   // all LDTMs done before next tile's MMA / TMA reuse
    }

    __syncthreads();
    if (tid == 0) {
        asm volatile("mbarrier.inval.shared.b64 [%0];" :: "r"(sb + SM_MBL) : "memory");
        asm volatile("mbarrier.inval.shared.b64 [%0];" :: "r"(sb + SM_MBM) : "memory");
    }
    if (wid == 0) TCGEN05_DEALLOC(tmem, 128);
#endif  // TC_OK
}

// ---------------- GAT aggregate + BN + ELU (two-phase, unroll x4) ------------
__global__ void __launch_bounds__(128)
gat_agg(const float* __restrict__ gamma, const float* __restrict__ beta,
        const float* __restrict__ mean, const float* __restrict__ var) {
    __shared__ float wgt[32][4];
    __shared__ int   sidx[32];
    __shared__ float smax[4];

    int n = blockIdx.x;
    int tid = threadIdx.x;
    int head = tid >> 5;
    int lane = tid & 31;
    int beg = g_rowbeg[n];
    int end = g_rowend[n];
    const float* hfeat = g_buf1;

    {
        float sd_h = g_sdst[n * 4 + head];
        float m = 0.f;
        for (int i = beg + lane; i < end; i += 32) {
            int s = g_csrc[i];
            float e = g_ssrc[s * 4 + head] + sd_h;
            e = (e >= 0.f) ? e : 0.2f * e;
            m = fmaxf(m, e);
        }
#pragma unroll
        for (int o = 16; o; o >>= 1) m = fmaxf(m, __shfl_xor_sync(~0u, m, o));
        if (lane == 0) smax[head] = m;
    }
    __syncthreads();

    int eh = tid & 3;
    int eo = tid >> 2;
    float sd_eh = g_sdst[n * 4 + eh];
    float m_eh = smax[eh];

    float acc0 = 0.f, acc1 = 0.f, ws = 0.f;
    int c = tid * 2;

    for (int base = beg; base < end; base += 32) {
        int cnt = min(32, end - base);
        {
            float w = 0.f;
            int s = -1;
            if (eo < cnt) {
                s = g_csrc[base + eo];
                float e = g_ssrc[s * 4 + eh] + sd_eh;
                e = (e >= 0.f) ? e : 0.2f * e;
                w = __expf(e - m_eh);
            }
            wgt[eo][eh] = w;
            if (eh == 0) sidx[eo] = s;
        }
        __syncthreads();
        int j = 0;
        for (; j + 4 <= cnt; j += 4) {
            float w0 = wgt[j][head], w1 = wgt[j + 1][head];
            float w2 = wgt[j + 2][head], w3 = wgt[j + 3][head];
            float2 h0 = *(const float2*)&hfeat[(size_t)sidx[j] * 256 + c];
            float2 h1 = *(const float2*)&hfeat[(size_t)sidx[j + 1] * 256 + c];
            float2 h2 = *(const float2*)&hfeat[(size_t)sidx[j + 2] * 256 + c];
            float2 h3 = *(const float2*)&hfeat[(size_t)sidx[j + 3] * 256 + c];
            ws += (w0 + w1) + (w2 + w3);
            acc0 = fmaf(w0, h0.x, acc0); acc1 = fmaf(w0, h0.y, acc1);
            acc0 = fmaf(w1, h1.x, acc0); acc1 = fmaf(w1, h1.y, acc1);
            acc0 = fmaf(w2, h2.x, acc0); acc1 = fmaf(w2, h2.y, acc1);
            acc0 = fmaf(w3, h3.x, acc0); acc1 = fmaf(w3, h3.y, acc1);
        }
        for (; j < cnt; j++) {
            float w = wgt[j][head];
            ws += w;
            float2 hv = *(const float2*)&hfeat[(size_t)sidx[j] * 256 + c];
            acc0 = fmaf(w, hv.x, acc0);
            acc1 = fmaf(w, hv.y, acc1);
        }
        __syncthreads();
    }

    float inv = 1.f / fmaxf(ws, 1e-9f);
    float o0 = acc0 * inv;
    float o1 = acc1 * inv;

    o0 = (o0 - mean[c]) * rsqrtf(var[c] + 1e-5f) * gamma[c] + beta[c];
    o1 = (o1 - mean[c + 1]) * rsqrtf(var[c + 1] + 1e-5f) * gamma[c + 1] + beta[c + 1];
    o0 = (o0 > 0.f) ? o0 : expm1f(o0);
    o1 = (o1 > 0.f) ? o1 : expm1f(o1);

    __nv_bfloat16 h0 = __float2bfloat16(o0);
    __nv_bfloat16 h1 = __float2bfloat16(o1);
    size_t idx2 = ((size_t)n * 256 + c) >> 1;
    ((__nv_bfloat162*)g_a_hi)[idx2] = __halves2bfloat162(h0, h1);
    ((__nv_bfloat162*)g_a_lo)[idx2] = __halves2bfloat162(
        __float2bfloat16(o0 - __bfloat162float(h0)),
        __float2bfloat16(o1 - __bfloat162float(h1)));
}

// ---------------------------------------------------------------------------
// Host-side tensormap construction (driver entry point; no -lcuda needed).
typedef CUresult (*PFN_encodeTiled)(
    CUtensorMap*, CUtensorMapDataType, cuuint32_t, void*,
    const cuuint64_t*, const cuuint64_t*, const cuuint32_t*, const cuuint32_t*,
    CUtensorMapInterleave, CUtensorMapSwizzle, CUtensorMapL2promotion,
    CUtensorMapFloatOOBfill);

static PFN_encodeTiled get_encoder() {
    static PFN_encodeTiled enc = nullptr;
    if (!enc) {
        void* fn = nullptr;
        cudaDriverEntryPointQueryResult st;
        cudaGetDriverEntryPointByVersion("cuTensorMapEncodeTiled", &fn, 12000,
                                         cudaEnableDefault, &st);
        enc = (PFN_encodeTiled)fn;
    }
    return enc;
}

static CUtensorMap make_map_bf16(void* base, unsigned long long rows) {
    CUtensorMap m{};
    cuuint64_t dims[2] = {256ull, rows};
    cuuint64_t strides[1] = {512ull};          // 256 bf16 per row
    cuuint32_t box[2] = {64u, 128u};           // 128B x 128 rows (SW128)
    cuuint32_t es[2] = {1u, 1u};
    PFN_encodeTiled enc = get_encoder();
    if (enc)
        enc(&m, CU_TENSOR_MAP_DATA_TYPE_BFLOAT16, 2, base, dims, strides, box, es,
            CU_TENSOR_MAP_INTERLEAVE_NONE, CU_TENSOR_MAP_SWIZZLE_128B,
            CU_TENSOR_MAP_L2_PROMOTION_L2_128B, CU_TENSOR_MAP_FLOAT_OOB_FILL_NONE);
    return m;
}

extern "C" void kernel_launch(void* const* d_in, const int* in_sizes, int n_in,
                              void* d_out, int out_size) {
    const float* x   = (const float*)d_in[0];
    const void*  ei  = d_in[1];
    const float* W1  = (const float*)d_in[2];
    const float* as1 = (const float*)d_in[3];
    const float* ad1 = (const float*)d_in[4];
    const float* g1  = (const float*)d_in[5];
    const float* b1  = (const float*)d_in[6];
    const float* m1  = (const float*)d_in[7];
    const float* v1  = (const float*)d_in[8];
    const float* W2  = (const float*)d_in[9];
    const float* as2 = (const float*)d_in[10];
    const float* ad2 = (const float*)d_in[11];
    const float* g2  = (const float*)d_in[12];
    const float* b2  = (const float*)d_in[13];
    const float* m2  = (const float*)d_in[14];
    const float* v2  = (const float*)d_in[15];
    const float* Wc  = (const float*)d_in[16];
    const float* bc  = (const float*)d_in[17];
    float* out = (float*)d_out;

    int N = in_sizes[0] / 256;
    int E = in_sizes[1] / 2;

    cudaFuncSetAttribute(gemm_tc, cudaFuncAttributeMaxDynamicSharedMemorySize,
                         SM_TOTAL);

    // tensormaps for A (activations) and B (weights)
    void *pAhi = nullptr, *pAlo = nullptr, *pBhi = nullptr, *pBlo = nullptr;
    cudaGetSymbolAddress(&pAhi, g_a_hi);
    cudaGetSymbolAddress(&pAlo, g_a_lo);
    cudaGetSymbolAddress(&pBhi, g_wb_hi);
    cudaGetSymbolAddress(&pBlo, g_wb_lo);
    CUtensorMap mAhi = make_map_bf16(pAhi, (unsigned long long)N);
    CUtensorMap mAlo = make_map_bf16(pAlo, (unsigned long long)N);
    CUtensorMap mBhi = make_map_bf16(pBhi, 256ull);
    CUtensorMap mBlo = make_map_bf16(pBlo, 256ull);

    int nx2 = N * 128;
    int nw2 = 256 * 256 / 2;
    int nc2 = 64 * 256 / 2;

    // gemm_tc stays the 4th launch for ncu.
    conv_split_x<<<(nx2 + 255) / 256, 256>>>(x, nx2);              // 1
    conv_split_w<<<(nw2 + 255) / 256, 256>>>(W1, nw2);             // 2
    detect_dtype<<<1, 1>>>(ei, N);                                 // 3
    gemm_tc<<<GEMM_GRID, 256, SM_TOTAL>>>(nullptr, nullptr, 0, N, 256,
                                          as1, ad1, mAhi, mAlo, mBhi, mBlo); // 4
    zero_counts<<<(N + 255) / 256, 256>>>(N);                      // 5
    hist_kernel<<<(E + 255) / 256, 256>>>(ei, E, N);               // 6
    alloc_rows<<<(N + 1023) / 1024, 1024>>>(N);                    // 7
    scatter_kernel<<<(E + 255) / 256, 256>>>(ei, E, N);            // 8
    gat_agg<<<N, 128>>>(g1, b1, m1, v1);                           // 9

    // --- layer 2 ---
    conv_split_w<<<(nw2 + 255) / 256, 256>>>(W2, nw2);
    gemm_tc<<<GEMM_GRID, 256, SM_TOTAL>>>(nullptr, nullptr, 0, N, 256,
                                          as2, ad2, mAhi, mAlo, mBhi, mBlo);
    gat_agg<<<N, 128>>>(g2, b2, m2, v2);

    // --- classifier ---
    conv_split_w<<<(nc2 + 255) / 256, 256>>>(Wc, nc2);
    gemm_tc<<<GEMM_GRID, 256, SM_TOTAL>>>(bc, out, 1, N, 64,
                                          nullptr, nullptr, mAhi, mAlo, mBhi, mBlo);
}